// round 9
// baseline (speedup 1.0000x reference)
#include <cuda_runtime.h>
#include <cuda_fp16.h>
#include <math.h>
#include <stdint.h>

#define DIMC 384
#define NH 6
#define HD 64
#define MLPD 1536
#define BATCH 8
#define SEQ 1024
#define ROWS (BATCH*SEQ)   /* 8192 */
#define BH (BATCH*NH)      /* 48 */
#define QKVW (3*DIMC)      /* 1152 */

typedef unsigned short u16;

// ---------------- scratch (single fp16 everywhere) ----------
__device__ u16 g_h[ROWS*DIMC];      // LN out
__device__ u16 g_qkv[ROWS*QKVW];    // QKV out
__device__ u16 g_at[ROWS*DIMC];     // attn out
__device__ u16 g_mlp[ROWS*MLPD];    // MLP hidden
__device__ u16 g_qw[QKVW*DIMC];
__device__ u16 g_pw[DIMC*DIMC];
__device__ u16 g_w1[MLPD*DIMC];
__device__ u16 g_w2[DIMC*MLPD];

__device__ __forceinline__ uint32_t smem_u32(const void* p) {
    uint32_t a;
    asm("{ .reg .u64 t; cvta.to.shared.u64 t, %1; cvt.u32.u64 %0, t; }" : "=r"(a) : "l"(p));
    return a;
}
__device__ __forceinline__ void ldm_x4(uint32_t* r, uint32_t addr) {
    asm volatile("ldmatrix.sync.aligned.m8n8.x4.shared.b16 {%0,%1,%2,%3}, [%4];"
                 : "=r"(r[0]), "=r"(r[1]), "=r"(r[2]), "=r"(r[3]) : "r"(addr));
}
__device__ __forceinline__ void ldm_x4_t(uint32_t* r, uint32_t addr) {
    asm volatile("ldmatrix.sync.aligned.m8n8.x4.trans.shared.b16 {%0,%1,%2,%3}, [%4];"
                 : "=r"(r[0]), "=r"(r[1]), "=r"(r[2]), "=r"(r[3]) : "r"(addr));
}
__device__ __forceinline__ void mma_f16(float* d, const uint32_t* a, const uint32_t* b) {
    asm volatile("mma.sync.aligned.m16n8k16.row.col.f32.f16.f16.f32 "
                 "{%0,%1,%2,%3}, {%4,%5,%6,%7}, {%8,%9}, {%0,%1,%2,%3};"
                 : "+f"(d[0]), "+f"(d[1]), "+f"(d[2]), "+f"(d[3])
                 : "r"(a[0]), "r"(a[1]), "r"(a[2]), "r"(a[3]), "r"(b[0]), "r"(b[1]));
}
__device__ __forceinline__ float f16_hi(float x) {
    return __half2float(__float2half_rn(x));
}
__device__ __forceinline__ uint32_t packh2(float x, float y) {
    __half2 t = __floats2half2_rn(x, y);
    return *(uint32_t*)&t;
}
__device__ __forceinline__ u16 h_as_u16(float x) {
    __half t = __float2half_rn(x);
    return *(u16*)&t;
}

// ---------------- all-weights convert: fp32 -> fp16, one launch ----------------
#define CVT_B0 432
#define CVT_B1 576
#define CVT_B2 1152
#define CVT_B3 1728
__global__ __launch_bounds__(256) void cvt_all(const float* __restrict__ s0,
                                               const float* __restrict__ s1,
                                               const float* __restrict__ s2,
                                               const float* __restrict__ s3,
                                               u16* d0, u16* d1, u16* d2, u16* d3)
{
    int blk = blockIdx.x;
    const float* src;
    u16* dst;
    int base;
    if (blk < CVT_B0)      { src = s0; dst = d0; base = 0; }
    else if (blk < CVT_B1) { src = s1; dst = d1; base = CVT_B0; }
    else if (blk < CVT_B2) { src = s2; dst = d2; base = CVT_B1; }
    else                   { src = s3; dst = d3; base = CVT_B2; }
    int idx = ((blk - base) * 256 + threadIdx.x) * 4;
    float4 v = *(const float4*)(src + idx);
    uint2 a;
    a.x = packh2(v.x, v.y); a.y = packh2(v.z, v.w);
    *(uint2*)(dst + idx) = a;
}

// ---------------- LayerNorm -> fp16 (shuffle reduce) ----------------
__global__ __launch_bounds__(128) void ln_kernel(const float* __restrict__ x,
                                                 const float* __restrict__ w,
                                                 const float* __restrict__ b,
                                                 u16* __restrict__ oh)
{
    int row = blockIdx.x;
    const float* xr = x + (size_t)row * DIMC;
    int t = threadIdx.x;
    int lane = t & 31, wrp = t >> 5;
    float v0 = xr[t], v1 = xr[t + 128], v2 = xr[t + 256];
    __shared__ float ws[4];

    float sum = v0 + v1 + v2;
    #pragma unroll
    for (int o = 16; o > 0; o >>= 1) sum += __shfl_xor_sync(0xFFFFFFFF, sum, o);
    if (lane == 0) ws[wrp] = sum;
    __syncthreads();
    float mean = (ws[0] + ws[1] + ws[2] + ws[3]) * (1.0f / DIMC);

    float d0 = v0 - mean, d1 = v1 - mean, d2 = v2 - mean;
    float sq = d0 * d0 + d1 * d1 + d2 * d2;
    #pragma unroll
    for (int o = 16; o > 0; o >>= 1) sq += __shfl_xor_sync(0xFFFFFFFF, sq, o);
    __syncthreads();
    if (lane == 0) ws[wrp] = sq;
    __syncthreads();
    float var = (ws[0] + ws[1] + ws[2] + ws[3]) * (1.0f / DIMC);
    float r = rsqrtf(var + 1e-5f);

    size_t base = (size_t)row * DIMC;
    #pragma unroll
    for (int p = 0; p < 3; p++) {
        int i = t + p * 128;
        float d = (p == 0 ? d0 : p == 1 ? d1 : d2);
        oh[base + i] = h_as_u16(d * r * w[i] + b[i]);
    }
}

// ================= mma.sync fp16 GEMM =================
// C[M,N] = A[M,K] @ W[N,K]^T, single fp16 operands, fp32 accum.
// 256 threads (8 warps 2x4), tile TM x 128, K-chunk 32.
// EPI 0: store fp16   EPI 1: +bias +res -> fp32   EPI 2: +bias, GELU, store fp16
#define LDS_ROW 80

template<int TM, int EPI>
__global__ __launch_bounds__(256) void mma_gemm(const u16* __restrict__ Ah_,
                                                const u16* __restrict__ Wh_,
                                                const float* __restrict__ bias,
                                                const float* __restrict__ res,
                                                float* __restrict__ C,
                                                u16* __restrict__ Ch,
                                                int M, int N, int K)
{
    constexpr int MI = TM / 32;
    constexpr int ABYTES = TM * LDS_ROW;
    constexpr int NPF = (TM == 128) ? 4 : 3;
    __shared__ __align__(128) char smem[ABYTES + 128 * LDS_ROW];
    uint32_t sbase = smem_u32(smem);

    int tid = threadIdx.x;
    int wid = tid >> 5;
    uint32_t lane = tid & 31;
    int wm = wid >> 2, wn = wid & 3;
    int n0 = blockIdx.x * 128, m0 = blockIdx.y * TM;

    float acc[MI][4][4];
    #pragma unroll
    for (int i = 0; i < MI; i++)
        #pragma unroll
        for (int j = 0; j < 4; j++)
            #pragma unroll
            for (int q = 0; q < 4; q++) acc[i][j][q] = 0.f;

    uint32_t aOff = (uint32_t)(wm * (TM / 2) + (lane & 15)) * LDS_ROW + (lane >> 4) * 16;
    uint32_t bOff = ABYTES
                    + (uint32_t)(wn * 32 + (lane & 7) + ((lane >> 4) << 3)) * LDS_ROW
                    + ((lane >> 3) & 1) * 16;

    const u16* s0 = Ah_ + (size_t)m0 * K;
    const u16* s1 = Wh_ + (size_t)n0 * K;

    int nchunks = K >> 5;
    uint4 pf[NPF];

    auto ld_chunk = [&](int k0) {
        #pragma unroll
        for (int p = 0; p < NPF; p++) {
            int t, i;
            if (TM == 128) { t = p >> 1; i = tid + (p & 1) * 256; }
            else           { t = (p == 0) ? 0 : 1; i = (p == 0) ? tid : tid + (p - 1) * 256; }
            int r = i >> 2, q = i & 3;
            const u16* src = (t == 0) ? s0 : s1;
            pf[p] = *(const uint4*)(src + (size_t)r * K + k0 + q * 8);
        }
    };
    auto st_chunk = [&]() {
        #pragma unroll
        for (int p = 0; p < NPF; p++) {
            int t, i;
            if (TM == 128) { t = p >> 1; i = tid + (p & 1) * 256; }
            else           { t = (p == 0) ? 0 : 1; i = (p == 0) ? tid : tid + (p - 1) * 256; }
            int r = i >> 2, q = i & 3;
            int off = (t == 0) ? 0 : ABYTES;
            *(uint4*)(smem + off + r * LDS_ROW + q * 16) = pf[p];
        }
    };

    ld_chunk(0);
    for (int c = 0; c < nchunks; c++) {
        __syncthreads();
        st_chunk();
        __syncthreads();
        if (c + 1 < nchunks) ld_chunk((c + 1) << 5);

        #pragma unroll
        for (int ks = 0; ks < 2; ks++) {
            uint32_t ko = ks * 32;
            uint32_t ah[MI][4], wh[2][4];
            #pragma unroll
            for (int mi = 0; mi < MI; mi++)
                ldm_x4(ah[mi], sbase + aOff + mi * (16 * LDS_ROW) + ko);
            #pragma unroll
            for (int j = 0; j < 2; j++)
                ldm_x4(wh[j], sbase + bOff + j * (16 * LDS_ROW) + ko);
            #pragma unroll
            for (int mi = 0; mi < MI; mi++)
                #pragma unroll
                for (int nj = 0; nj < 4; nj++)
                    mma_f16(acc[mi][nj], ah[mi], &wh[nj >> 1][(nj & 1) * 2]);
        }
    }

    // ---- epilogue ----
    #pragma unroll
    for (int mi = 0; mi < MI; mi++) {
        int r0 = m0 + wm * (TM / 2) + mi * 16 + (int)(lane >> 2);
        #pragma unroll
        for (int nj = 0; nj < 4; nj++) {
            int col = n0 + wn * 32 + nj * 8 + (int)(lane & 3) * 2;
            float v[4];
            #pragma unroll
            for (int q = 0; q < 4; q++) v[q] = acc[mi][nj][q];
            if (EPI == 1 || EPI == 2) {
                float2 bb = *(const float2*)(bias + col);
                v[0] += bb.x; v[1] += bb.y; v[2] += bb.x; v[3] += bb.y;
            }
            if (EPI == 1) {
                float2 ra = *(const float2*)(res + (size_t)r0 * N + col);
                float2 rb = *(const float2*)(res + (size_t)(r0 + 8) * N + col);
                v[0] += ra.x; v[1] += ra.y; v[2] += rb.x; v[3] += rb.y;
            }
            if (EPI == 2) {
                #pragma unroll
                for (int q = 0; q < 4; q++)
                    v[q] = 0.5f * v[q] * (1.0f + erff(v[q] * 0.7071067811865476f));
            }
            if (EPI == 1) {
                float2 o0; o0.x = v[0]; o0.y = v[1];
                float2 o1; o1.x = v[2]; o1.y = v[3];
                *(float2*)(C + (size_t)r0 * N + col) = o0;
                *(float2*)(C + (size_t)(r0 + 8) * N + col) = o1;
            } else {
                *(uint32_t*)(Ch + (size_t)r0 * N + col)       = packh2(v[0], v[1]);
                *(uint32_t*)(Ch + (size_t)(r0 + 8) * N + col) = packh2(v[2], v[3]);
            }
        }
    }
}

// ================= tensor-core L2Q attention (single fp16) =================
// 128 queries x one (b,h) per block, 8 warps x 16 query rows.
// S = Q@K^T, f = relu(a's^2+b's+g); P rounded to fp16, rowsum over ROUNDED P.
#define AROW 144
#define A_Q 0
#define A_K 18432
#define A_V 27648
#define ATTN_SMEM 36864

__global__ __launch_bounds__(256) void attn_mma(const u16* __restrict__ qkv,
                                                const float* __restrict__ alpha,
                                                const float* __restrict__ beta,
                                                const float* __restrict__ gamma,
                                                u16* __restrict__ oh)
{
    extern __shared__ char sm[];
    uint32_t sb = smem_u32(sm);
    int tid = threadIdx.x;
    int wid = tid >> 5;
    uint32_t lane = tid & 31;
    int bh = blockIdx.y;
    int b = bh / NH, h = bh % NH;
    int q0 = blockIdx.x * 128;
    float al2 = alpha[h] * 0.015625f;
    float be2 = beta[h] * 0.125f;
    float ga = gamma[h];

    size_t rowbase = (size_t)b * SEQ * QKVW;

    // ---- stage Q tile (128 x 64) ----
    #pragma unroll
    for (int p = 0; p < 4; p++) {
        int i = tid + p * 256;
        int r = i >> 3, q = i & 7;
        uint4 v = *(const uint4*)(qkv + rowbase + (size_t)(q0 + r) * QKVW + h * HD + q * 8);
        *(uint4*)(sm + A_Q + r * AROW + q * 16) = v;
    }
    __syncthreads();

    uint32_t aOffQ = (uint32_t)(wid * 16 + (lane & 15)) * AROW + (lane >> 4) * 16;
    uint32_t ah[4][4];
    #pragma unroll
    for (int ks = 0; ks < 4; ks++)
        ldm_x4(ah[ks], sb + A_Q + aOffQ + ks * 32);

    float o[8][4];
    #pragma unroll
    for (int d = 0; d < 8; d++)
        #pragma unroll
        for (int q = 0; q < 4; q++) o[d][q] = 0.f;
    float rs0 = 0.f, rs1 = 0.f;

    uint32_t kb = (uint32_t)((lane & 7) + ((lane >> 4) << 3)) * AROW + ((lane >> 3) & 1) * 16;
    uint32_t vb = (uint32_t)((lane & 7) + (((lane >> 3) & 1) << 3)) * AROW + (lane >> 4) * 16;

    uint4 pf[4];
    auto ld_kv = [&](int c) {
        #pragma unroll
        for (int p = 0; p < 4; p++) {
            int t = p >> 1;
            int coloff = (t == 0) ? (DIMC + h * HD) : (2 * DIMC + h * HD);
            int i = tid + (p & 1) * 256;
            int r = i >> 3, q = i & 7;
            pf[p] = *(const uint4*)(qkv + rowbase + (size_t)(c * 64 + r) * QKVW + coloff + q * 8);
        }
    };
    auto st_kv = [&]() {
        #pragma unroll
        for (int p = 0; p < 4; p++) {
            int t = p >> 1;
            int soff = (t == 0) ? A_K : A_V;
            int i = tid + (p & 1) * 256;
            int r = i >> 3, q = i & 7;
            *(uint4*)(sm + soff + r * AROW + q * 16) = pf[p];
        }
    };

    ld_kv(0);
    for (int c = 0; c < SEQ / 64; c++) {
        __syncthreads();
        st_kv();
        __syncthreads();
        if (c + 1 < SEQ / 64) ld_kv(c + 1);

        // ---- S = Q @ K^T ----
        float s[8][4];
        #pragma unroll
        for (int nf = 0; nf < 8; nf++)
            #pragma unroll
            for (int q = 0; q < 4; q++) s[nf][q] = 0.f;
        #pragma unroll
        for (int ks = 0; ks < 4; ks++) {
            uint32_t khf[4][4];
            #pragma unroll
            for (int g = 0; g < 4; g++)
                ldm_x4(khf[g], sb + A_K + kb + g * (16 * AROW) + ks * 32);
            #pragma unroll
            for (int nf = 0; nf < 8; nf++)
                mma_f16(s[nf], ah[ks], &khf[nf >> 1][(nf & 1) * 2]);
        }
        // ---- activation ----
        #pragma unroll
        for (int nf = 0; nf < 8; nf++) {
            #pragma unroll
            for (int q = 0; q < 4; q++) {
                float xv = s[nf][q];
                float f = fmaf(al2 * xv, xv, fmaf(be2, xv, ga));
                s[nf][q] = fmaxf(f, 0.f);
            }
        }
        // ---- O += round(P) @ V ; rowsum over ROUNDED P ----
        #pragma unroll
        for (int ks = 0; ks < 4; ks++) {
            float h00 = f16_hi(s[2*ks][0]), h01 = f16_hi(s[2*ks][1]);
            float h02 = f16_hi(s[2*ks][2]), h03 = f16_hi(s[2*ks][3]);
            float h10 = f16_hi(s[2*ks+1][0]), h11 = f16_hi(s[2*ks+1][1]);
            float h12 = f16_hi(s[2*ks+1][2]), h13 = f16_hi(s[2*ks+1][3]);
            rs0 += h00 + h01 + h10 + h11;
            rs1 += h02 + h03 + h12 + h13;
            uint32_t ph[4];
            ph[0] = packh2(h00, h01); ph[1] = packh2(h02, h03);
            ph[2] = packh2(h10, h11); ph[3] = packh2(h12, h13);

            uint32_t vhf[4][4];
            #pragma unroll
            for (int g = 0; g < 4; g++)
                ldm_x4_t(vhf[g], sb + A_V + vb + ks * (16 * AROW) + g * 32);
            #pragma unroll
            for (int df = 0; df < 8; df++)
                mma_f16(o[df], ph, &vhf[df >> 1][(df & 1) * 2]);
        }
    }

    rs0 += __shfl_xor_sync(0xFFFFFFFF, rs0, 1);
    rs0 += __shfl_xor_sync(0xFFFFFFFF, rs0, 2);
    rs1 += __shfl_xor_sync(0xFFFFFFFF, rs1, 1);
    rs1 += __shfl_xor_sync(0xFFFFFFFF, rs1, 2);
    float inv0 = 1.0f / (rs0 + 1e-6f);
    float inv1 = 1.0f / (rs1 + 1e-6f);

    int grow = b * SEQ + q0 + wid * 16 + (int)(lane >> 2);
    #pragma unroll
    for (int df = 0; df < 8; df++) {
        int col = h * HD + df * 8 + (int)(lane & 3) * 2;
        *(uint32_t*)(oh + (size_t)grow * DIMC + col)       = packh2(o[df][0] * inv0, o[df][1] * inv0);
        *(uint32_t*)(oh + (size_t)(grow + 8) * DIMC + col) = packh2(o[df][2] * inv1, o[df][3] * inv1);
    }
}

// ---------------- launch ------------------------------------------------------
extern "C" void kernel_launch(void* const* d_in, const int* in_sizes, int n_in,
                              void* d_out, int out_size)
{
    const float* x      = (const float*)d_in[0];
    const float* qkv_w  = (const float*)d_in[1];
    const float* proj_w = (const float*)d_in[2];
    const float* proj_b = (const float*)d_in[3];
    const float* alpha  = (const float*)d_in[4];
    const float* beta   = (const float*)d_in[5];
    const float* gamma  = (const float*)d_in[6];
    const float* ln1_w  = (const float*)d_in[7];
    const float* ln1_b  = (const float*)d_in[8];
    const float* ln2_w  = (const float*)d_in[9];
    const float* ln2_b  = (const float*)d_in[10];
    const float* w1     = (const float*)d_in[11];
    const float* b1     = (const float*)d_in[12];
    const float* w2     = (const float*)d_in[13];
    const float* b2     = (const float*)d_in[14];
    float* out = (float*)d_out;

    u16 *hh, *qv, *at, *mp, *qw, *pw, *w1h, *w2h;
    cudaGetSymbolAddress((void**)&hh,  g_h);
    cudaGetSymbolAddress((void**)&qv,  g_qkv);
    cudaGetSymbolAddress((void**)&at,  g_at);
    cudaGetSymbolAddress((void**)&mp,  g_mlp);
    cudaGetSymbolAddress((void**)&qw,  g_qw);
    cudaGetSymbolAddress((void**)&pw,  g_pw);
    cudaGetSymbolAddress((void**)&w1h, g_w1);
    cudaGetSymbolAddress((void**)&w2h, g_w2);

    cudaFuncSetAttribute(attn_mma, cudaFuncAttributeMaxDynamicSharedMemorySize, ATTN_SMEM);

    // 0) convert all weights to fp16 (one launch)
    cvt_all<<<CVT_B3, 256>>>(qkv_w, proj_w, w1, w2, qw, pw, w1h, w2h);
    // 1) LN1 -> fp16
    ln_kernel<<<ROWS, 128>>>(x, ln1_w, ln1_b, hh);
    // 2) QKV gemm -> fp16
    mma_gemm<128, 0><<<dim3(QKVW / 128, ROWS / 128), 256>>>(
        hh, qw, nullptr, nullptr, nullptr, qv, ROWS, QKVW, DIMC);
    // 3) attention -> fp16
    attn_mma<<<dim3(SEQ / 128, BH), 256, ATTN_SMEM>>>(qv, alpha, beta, gamma, at);
    // 4) proj + bias + residual(x) -> out fp32
    mma_gemm<64, 1><<<dim3(DIMC / 128, ROWS / 64), 256>>>(
        at, pw, proj_b, x, out, nullptr, ROWS, DIMC, DIMC);
    // 5) LN2 -> fp16
    ln_kernel<<<ROWS, 128>>>(out, ln2_w, ln2_b, hh);
    // 6) MLP1 + bias + GELU -> fp16
    mma_gemm<128, 2><<<dim3(MLPD / 128, ROWS / 128), 256>>>(
        hh, w1h, b1, nullptr, nullptr, mp, ROWS, MLPD, DIMC);
    // 7) MLP2 + bias + residual(out) -> out fp32
    mma_gemm<64, 1><<<dim3(DIMC / 128, ROWS / 64), 256>>>(
        mp, w2h, b2, out, out, nullptr, ROWS, DIMC, MLPD);
}